// round 14
// baseline (speedup 1.0000x reference)
#include <cuda_runtime.h>

#define NN 20000
#define EE 50000
#define BB 128
#define HH 64
#define FEATD 28
#define NTYPES 100
#define EDIM 5
#define MPI 3
#define S2S 4

#define TE 64                        // edges/nodes per GEMM tile
#define EDGETILES (EE / TE + EDIM)   // 786
#define ROOTTILES ((NN + TE - 1) / TE)  // 313
#define GRIDMP (ROOTTILES + EDGETILES)  // 1099
#define ZTOT (NN * HH / 4)           // float4 count of one h buffer
#define SMAX 160                     // cached h rows per graph in k_s2s_all
#define SA 512                       // smem softmax-weight slots per graph
#define SCB ((EE + 255) / 256)       // scatter blocks in fused front kernel

typedef unsigned long long u64;

// ---------------- scratch (device globals; no allocation allowed) ----------
__device__ float g_hA[NN * HH];
__device__ float g_hB[NN * HH];
__device__ float g_hC[NN * HH];
__device__ float g_Wmat[EDIM * HH * HH];
__device__ float g_WihT[2 * HH * 4 * HH];   // [128][256] transposed W_ih
__device__ float g_WhhT[HH * 4 * HH];       // [64][256]  transposed W_hh
__device__ float g_a[NN];                   // softmax spill (len > SA only)
__device__ int   g_seg[BB + 1];
__device__ int   g_tcnt[EDIM];
__device__ int   g_tptr[EDIM];
__device__ int   g_toff[EDIM + 1];
__device__ int   g_tileoff[EDIM + 1];
__device__ int   g_psrc[EE];
__device__ int   g_pdst[EE];
__device__ int   g_done = 0;

__device__ __forceinline__ float* hsel(int id) {
    return id == 0 ? g_hA : (id == 1 ? g_hB : g_hC);
}

__device__ __forceinline__ void red_v4(float* p, float a, float b, float c, float d) {
    asm volatile("red.global.add.v4.f32 [%0], {%1, %2, %3, %4};"
                 :: "l"(p), "f"(a), "f"(b), "f"(c), "f"(d) : "memory");
}

__device__ __forceinline__ u64 pack2(float x) {
    u64 r; asm("mov.b64 %0, {%1, %1};" : "=l"(r) : "f"(x)); return r;
}
__device__ __forceinline__ void fma2(u64& d, u64 a, u64 b) {
    asm("fma.rn.f32x2 %0, %1, %2, %0;" : "+l"(d) : "l"(a), "l"(b));
}
__device__ __forceinline__ float2 unpack2(u64 v) {
    float2 f; asm("mov.b64 {%0, %1}, %2;" : "=f"(f.x), "=f"(f.y) : "l"(v));
    return f;
}

// ======== setup: seg bounds + type hist + (last block) scan ================
__global__ void k_setup(const int* __restrict__ batch,
                        const int* __restrict__ etype) {
    __shared__ int sh[EDIM];
    int tid = threadIdx.x;
    int gid = blockIdx.x * blockDim.x + tid;

    if (tid < EDIM) sh[tid] = 0;

    if (blockIdx.x == 0 && tid <= BB) {
        if (tid == BB) g_seg[BB] = NN;
        else {
            int lo = 0, hi = NN;
            while (lo < hi) {
                int mid = (lo + hi) >> 1;
                if (batch[mid] < tid) lo = mid + 1; else hi = mid;
            }
            g_seg[tid] = lo;
        }
    }
    __syncthreads();

    if (gid < EE) atomicAdd(&sh[etype[gid]], 1);
    __syncthreads();
    if (tid < EDIM) atomicAdd(&g_tcnt[tid], sh[tid]);
    __syncthreads();

    if (tid == 0) {
        __threadfence();
        int old = atomicAdd(&g_done, 1);
        if (old == (int)gridDim.x - 1) {
            int off = 0, toff = 0;
            for (int t = 0; t < EDIM; t++) {
                int n = atomicAdd(&g_tcnt[t], 0);
                g_toff[t] = off;
                g_tileoff[t] = toff;
                g_tptr[t] = off;
                off += n;
                toff += (n + TE - 1) / TE;
                g_tcnt[t] = 0;
            }
            g_toff[EDIM] = off;
            g_tileoff[EDIM] = toff;
            g_done = 0;
        }
    }
}

// ======== fused front: scatter + wmat + weight transposes + embedding ======
// Scatter now uses block-aggregated reservation: 5 global atomics per block
// instead of 256 contended atomics on 5 addresses.
__global__ void k_front(const int* __restrict__ etype,
                        const int* __restrict__ src,
                        const int* __restrict__ dst,
                        const float* __restrict__ W_e1,
                        const float* __restrict__ b_e1,
                        const float* __restrict__ W_e2,
                        const float* __restrict__ b_e2,
                        const float* __restrict__ feat,
                        const int* __restrict__ ntype,
                        const float* __restrict__ W_emb,
                        const float* __restrict__ b_emb,
                        const float* __restrict__ W_ih,
                        const float* __restrict__ W_hh) {
    int tid = threadIdx.x;
    if (blockIdx.x < SCB) {
        __shared__ int cnt[EDIM];
        __shared__ int basep[EDIM];
        int e = blockIdx.x * 256 + tid;
        int t = (e < EE) ? etype[e] : -1;
        if (tid < EDIM) cnt[tid] = 0;
        __syncthreads();
        int loc = 0;
        if (t >= 0) loc = atomicAdd(&cnt[t], 1);
        __syncthreads();
        if (tid < EDIM && cnt[tid] > 0)
            basep[tid] = atomicAdd(&g_tptr[tid], cnt[tid]);
        __syncthreads();
        if (t >= 0) {
            int pos = basep[t] + loc;
            g_psrc[pos] = src[e];
            g_pdst[pos] = dst[e];
        }
    } else if (blockIdx.x < SCB + 64) {
        __shared__ float hr[EDIM][HH];
        __shared__ float part[4][EDIM][HH];
        int wb = blockIdx.x - SCB;
        if (tid < HH) {
#pragma unroll
            for (int t = 0; t < EDIM; t++)
                hr[t][tid] = fmaxf(W_e1[t * HH + tid] + b_e1[tid], 0.f);
        }
        __syncthreads();
        int jc = tid >> 6;
        int c = tid & 63;
        int idx = wb * 64 + c;
        float a0 = 0.f, a1 = 0.f, a2 = 0.f, a3 = 0.f, a4 = 0.f;
#pragma unroll
        for (int jj = 0; jj < 16; jj++) {
            int j = jc * 16 + jj;
            float w = W_e2[j * (HH * HH) + idx];
            a0 += hr[0][j] * w;
            a1 += hr[1][j] * w;
            a2 += hr[2][j] * w;
            a3 += hr[3][j] * w;
            a4 += hr[4][j] * w;
        }
        part[jc][0][c] = a0; part[jc][1][c] = a1; part[jc][2][c] = a2;
        part[jc][3][c] = a3; part[jc][4][c] = a4;
        __syncthreads();
        if (jc == 0) {
            float bb = b_e2[idx];
#pragma unroll
            for (int t = 0; t < EDIM; t++)
                g_Wmat[t * HH * HH + idx] =
                    bb + part[0][t][c] + part[1][t][c] + part[2][t][c] + part[3][t][c];
        }
    } else if (blockIdx.x < SCB + 65) {
        for (int idx = tid; idx < 2 * HH * 4 * HH; idx += 256) {
            int k = idx >> 8;
            int j = idx & 255;
            g_WihT[idx] = W_ih[j * (2 * HH) + k];
        }
    } else if (blockIdx.x < SCB + 66) {
        for (int idx = tid; idx < HH * 4 * HH; idx += 256) {
            int k = idx >> 8;
            int j = idx & 255;
            g_WhhT[idx] = W_hh[j * HH + k];
        }
    } else {
        __shared__ float sf[4][FEATD];
        int blk = blockIdx.x - SCB - 66;      // 0..4999
        int l = tid >> 6;
        int o = tid & 63;
        int node = blk * 4 + l;
        g_hB[blk * 256 + tid] = 0.f;
        if (o < FEATD) sf[l][o] = feat[node * FEATD + o];
        __syncthreads();
        int t = ntype[node];
        float acc = b_emb[o] + W_emb[t * HH + o];
#pragma unroll
        for (int f = 0; f < FEATD; f++)
            acc += sf[l][f] * W_emb[(NTYPES + f) * HH + o];
        g_hA[node * HH + o] = acc;
    }
}

// ======== fused MP iteration: root + edge GEMM tiles, TE=64 ================
// 1099 blocks (~7.4/SM demand) for cross-block latency hiding. Per thread:
// 4 rows x 8 outs as 2 row-pairs via fma.rn.f32x2; the 4 rows arrive in ONE
// 16B-aligned LDS.128. W read directly from global (L1-resident broadcast).
__global__ __launch_bounds__(128) void k_mp(int in_id, int out_id, int zero_id,
                                            int iter,
                                            const float* __restrict__ roots,
                                            const float* __restrict__ bias) {
    const float* hin = hsel(in_id);
    float* hout      = hsel(out_id);
    int tid = threadIdx.x;

    if (zero_id >= 0) {
        float4* z = (float4*)hsel(zero_id);
        const int chunk = (ZTOT + GRIDMP - 1) / GRIDMP;
        int lo = blockIdx.x * chunk;
        int hiz = lo + chunk; if (hiz > ZTOT) hiz = ZTOT;
        for (int i = lo + tid; i < hiz; i += 128)
            z[i] = make_float4(0.f, 0.f, 0.f, 0.f);
    }

    __shared__ __align__(16) float hsT[HH][TE + 8];   // [k][row], 18KB
    __shared__ int sdst[TE];
    __shared__ int ssrc[TE];

    bool is_root = blockIdx.x < (unsigned)ROOTTILES;
    const float* W;
    int base;

    if (is_root) {
        base = blockIdx.x * TE;
        W = roots + iter * HH * HH;
        if (tid < TE) {
            int node = base + tid;
            bool ok = node < NN;
            sdst[tid] = ok ? node : -1;
            ssrc[tid] = ok ? node : 0;
        }
    } else {
        int tb = blockIdx.x - ROOTTILES;
        if (tb >= g_tileoff[EDIM]) return;
        int t = 0;
        while (tb >= g_tileoff[t + 1]) t++;
        base = g_toff[t] + (tb - g_tileoff[t]) * TE;
        int hi = g_toff[t + 1];
        W = g_Wmat + t * HH * HH;
        if (tid < TE) {
            int p = base + tid;
            bool ok = p < hi;
            sdst[tid] = ok ? g_pdst[p] : -1;
            ssrc[tid] = ok ? g_psrc[p] : 0;
        }
    }
    __syncthreads();

    // cooperative gather: 4 threads per row, 32 rows per pass, 2 passes.
    {
        int q = tid & 3;               // quarter of the row (16 floats)
        int er = tid >> 2;             // 0..31
#pragma unroll
        for (int pass = 0; pass < 2; pass++) {
            int e = pass * 32 + er;
            int s = ssrc[e];
            const float4* hr = (const float4*)(hin + s * HH + q * 16);
#pragma unroll
            for (int j = 0; j < 4; j++) {
                float4 v = hr[j];
                int k = q * 16 + j * 4;
                hsT[k + 0][e] = v.x;
                hsT[k + 1][e] = v.y;
                hsT[k + 2][e] = v.z;
                hsT[k + 3][e] = v.w;
            }
        }
    }
    __syncthreads();

    int rg = tid >> 3;   // 0..15 row group (4 rows = 2 row-pairs)
    int og = tid & 7;    // 0..7  out group (8 outs)

    u64 acc2[2][8];
    if (is_root) {
        float4 b0 = *(const float4*)(bias + iter * HH + og * 8);
        float4 b1 = *(const float4*)(bias + iter * HH + og * 8 + 4);
        float bb[8] = {b0.x, b0.y, b0.z, b0.w, b1.x, b1.y, b1.z, b1.w};
#pragma unroll
        for (int ap = 0; ap < 2; ap++)
#pragma unroll
            for (int b = 0; b < 8; b++) acc2[ap][b] = pack2(bb[b]);
    } else {
#pragma unroll
        for (int ap = 0; ap < 2; ap++)
#pragma unroll
            for (int b = 0; b < 8; b++) acc2[ap][b] = 0ull;
    }

    const float4* Wv = (const float4*)(W + og * 8);   // row k: Wv[k*16], Wv[k*16+1]

#pragma unroll 8
    for (int k = 0; k < HH; k++) {
        // one LDS.128 delivers all 4 rows (16B aligned: stride 72 floats)
        double2 ha = *(const double2*)&hsT[k][rg * 4];
        u64 h0 = __double_as_longlong(ha.x);
        u64 h1 = __double_as_longlong(ha.y);
        float4 w0 = __ldg(Wv + k * 16);
        float4 w1 = __ldg(Wv + k * 16 + 1);
        u64 wb0 = pack2(w0.x), wb1 = pack2(w0.y), wb2 = pack2(w0.z), wb3 = pack2(w0.w);
        u64 wb4 = pack2(w1.x), wb5 = pack2(w1.y), wb6 = pack2(w1.z), wb7 = pack2(w1.w);

        fma2(acc2[0][0], h0, wb0); fma2(acc2[0][1], h0, wb1);
        fma2(acc2[0][2], h0, wb2); fma2(acc2[0][3], h0, wb3);
        fma2(acc2[0][4], h0, wb4); fma2(acc2[0][5], h0, wb5);
        fma2(acc2[0][6], h0, wb6); fma2(acc2[0][7], h0, wb7);

        fma2(acc2[1][0], h1, wb0); fma2(acc2[1][1], h1, wb1);
        fma2(acc2[1][2], h1, wb2); fma2(acc2[1][3], h1, wb3);
        fma2(acc2[1][4], h1, wb4); fma2(acc2[1][5], h1, wb5);
        fma2(acc2[1][6], h1, wb6); fma2(acc2[1][7], h1, wb7);
    }

#pragma unroll
    for (int ap = 0; ap < 2; ap++) {
        float2 u0 = unpack2(acc2[ap][0]);
        float2 u1 = unpack2(acc2[ap][1]);
        float2 u2 = unpack2(acc2[ap][2]);
        float2 u3 = unpack2(acc2[ap][3]);
        float2 u4 = unpack2(acc2[ap][4]);
        float2 u5 = unpack2(acc2[ap][5]);
        float2 u6 = unpack2(acc2[ap][6]);
        float2 u7 = unpack2(acc2[ap][7]);
        int dlo = sdst[rg * 4 + 2 * ap];
        int dhi = sdst[rg * 4 + 2 * ap + 1];
        if (dlo >= 0) {
            float* dr = hout + dlo * HH + og * 8;
            red_v4(dr,     u0.x, u1.x, u2.x, u3.x);
            red_v4(dr + 4, u4.x, u5.x, u6.x, u7.x);
        }
        if (dhi >= 0) {
            float* dr = hout + dhi * HH + og * 8;
            red_v4(dr,     u0.y, u1.y, u2.y, u3.y);
            red_v4(dr + 4, u4.y, u5.y, u6.y, u7.y);
        }
    }
}

// ======== fully fused Set2Set: 4 iterations + output MLP ===================
__global__ __launch_bounds__(256) void k_s2s_all(const float* __restrict__ b_ih,
                                                 const float* __restrict__ b_hh,
                                                 const float* __restrict__ W_o1,
                                                 const float* __restrict__ b_o1,
                                                 const float* __restrict__ W_o2,
                                                 const float* __restrict__ b_o2,
                                                 float* __restrict__ out) {
    const float* h = g_hA;          // final node states after MPI=3 (A->B->C->A)
    int b = blockIdx.x;
    int tid = threadIdx.x;

    __shared__ float hcache[SMAX * HH];   // 40KB
    __shared__ float sa[SA];
    __shared__ float qs[2 * HH];
    __shared__ float gates[4 * HH];
    __shared__ float q[HH];
    __shared__ float hx_s[HH];
    __shared__ float cx_s[HH];
    __shared__ float red[256];
    __shared__ float r4[4][HH];

    int s = g_seg[b], t = g_seg[b + 1];
    int len = t - s;
    int nc = len < SMAX ? len : SMAX;

    {
        float4* d4 = (float4*)hcache;
        const float4* s4 = (const float4*)(h + s * HH);
        int tot = nc * (HH / 4);
        for (int i = tid; i < tot; i += 256) d4[i] = s4[i];
    }
    if (tid < 2 * HH) qs[tid] = 0.f;
    if (tid < HH) { hx_s[tid] = 0.f; cx_s[tid] = 0.f; }
    __syncthreads();

    float ev[8];   // per-thread scores (supports len <= 2048)

    for (int it = 0; it < S2S; it++) {
        {
            float g0 = b_ih[tid];
            float g1 = b_hh[tid];
#pragma unroll 8
            for (int k = 0; k < 2 * HH; k++) g0 += qs[k] * g_WihT[k * 256 + tid];
#pragma unroll 8
            for (int k = 0; k < HH; k++)     g1 += hx_s[k] * g_WhhT[k * 256 + tid];
            gates[tid] = g0 + g1;
        }
        __syncthreads();
        if (tid < HH) {
            float ig = gates[tid], fg = gates[HH + tid];
            float gg = gates[2 * HH + tid], og = gates[3 * HH + tid];
            float si = 1.f / (1.f + expf(-ig));
            float sf = 1.f / (1.f + expf(-fg));
            float so = 1.f / (1.f + expf(-og));
            float c = sf * cx_s[tid] + si * tanhf(gg);
            cx_s[tid] = c;
            float hx = so * tanhf(c);
            hx_s[tid] = hx;
            q[tid] = hx;
        }
        __syncthreads();

        float lmax = -1e30f;
        const float4* q4 = (const float4*)q;
        {
            int i = 0;
            for (int l = tid; l < len && i < 8; l += 256, i++) {
                const float4* hr = (l < nc) ? (const float4*)&hcache[l * HH]
                                            : (const float4*)(h + (s + l) * HH);
                float e = 0.f;
#pragma unroll
                for (int k = 0; k < HH / 4; k++) {
                    float4 hv = hr[k];
                    float4 qv = q4[k];
                    e += hv.x * qv.x + hv.y * qv.y + hv.z * qv.z + hv.w * qv.w;
                }
                ev[i] = e;
                lmax = fmaxf(lmax, e);
            }
        }
        red[tid] = lmax; __syncthreads();
        for (int w = 128; w > 0; w >>= 1) {
            if (tid < w) red[tid] = fmaxf(red[tid], red[tid + w]);
            __syncthreads();
        }
        float m = red[0];
        __syncthreads();

        float lsum = 0.f;
        {
            int i = 0;
            for (int l = tid; l < len && i < 8; l += 256, i++) {
                float a = expf(ev[i] - m);
                if (l < SA) sa[l] = a; else g_a[s + l] = a;
                lsum += a;
            }
        }
        red[tid] = lsum; __syncthreads();
        for (int w = 128; w > 0; w >>= 1) {
            if (tid < w) red[tid] += red[tid + w];
            __syncthreads();
        }
        float denom = red[0];
        if (denom == 0.f) denom = 1.f;
        __syncthreads();

        {
            int part = tid >> 6;
            int o = tid & 63;
            float r = 0.f;
            for (int l = part; l < len; l += 4) {
                float av = (l < SA) ? sa[l] : g_a[s + l];
                float hv = (l < nc) ? hcache[l * HH + o] : h[(s + l) * HH + o];
                r += av * hv;
            }
            r4[part][o] = r;
        }
        __syncthreads();
        if (tid < HH) {
            float r = (r4[0][tid] + r4[1][tid] + r4[2][tid] + r4[3][tid]) / denom;
            qs[tid]      = q[tid];
            qs[HH + tid] = r;
        }
        __syncthreads();
    }

    if (tid < HH) {
        float v = b_o1[tid];
#pragma unroll 8
        for (int k = 0; k < 2 * HH; k++) v += qs[k] * W_o1[k * HH + tid];
        v = fmaxf(v, 0.f);
        red[tid] = v * W_o2[tid];
    }
    __syncthreads();
    for (int w = 32; w > 0; w >>= 1) {
        if (tid < w) red[tid] += red[tid + w];
        __syncthreads();
    }
    if (tid == 0) out[b] = red[0] + b_o2[0];
}

// ---------------------------------------------------------------------------
extern "C" void kernel_launch(void* const* d_in, const int* in_sizes, int n_in,
                              void* d_out, int out_size) {
    const float* node_feat = (const float*)d_in[0];
    const int*   node_type = (const int*)d_in[1];
    const int*   edge_index= (const int*)d_in[2];
    const int*   etype     = (const int*)d_in[3];
    const int*   batch     = (const int*)d_in[4];
    const float* W_emb     = (const float*)d_in[5];
    const float* b_emb     = (const float*)d_in[6];
    const float* W_e1      = (const float*)d_in[7];
    const float* b_e1      = (const float*)d_in[8];
    const float* W_e2      = (const float*)d_in[9];
    const float* b_e2      = (const float*)d_in[10];
    const float* roots     = (const float*)d_in[11];
    const float* conv_bias = (const float*)d_in[12];
    const float* W_ih      = (const float*)d_in[13];
    const float* W_hh      = (const float*)d_in[14];
    const float* b_ih      = (const float*)d_in[15];
    const float* b_hh      = (const float*)d_in[16];
    const float* W_o1      = (const float*)d_in[17];
    const float* b_o1      = (const float*)d_in[18];
    const float* W_o2      = (const float*)d_in[19];
    const float* b_o2      = (const float*)d_in[20];
    float* out = (float*)d_out;

    const int* src = edge_index;
    const int* dst = edge_index + EE;

    k_setup<<<(EE + 255) / 256, 256>>>(batch, etype);
    k_front<<<SCB + 66 + NN / 4, 256>>>(etype, src, dst,
                                        W_e1, b_e1, W_e2, b_e2,
                                        node_feat, node_type, W_emb, b_emb,
                                        W_ih, W_hh);

    // 3-buffer rotation: (in, out, zero)
    k_mp<<<GRIDMP, 128>>>(0, 1, 2, 0, roots, conv_bias);  // A->B, zero C
    k_mp<<<GRIDMP, 128>>>(1, 2, 0, 1, roots, conv_bias);  // B->C, zero A
    k_mp<<<GRIDMP, 128>>>(2, 0, -1, 2, roots, conv_bias); // C->A

    k_s2s_all<<<BB, 256>>>(b_ih, b_hh, W_o1, b_o1, W_o2, b_o2, out);
}

// round 15
// speedup vs baseline: 1.2030x; 1.2030x over previous
#include <cuda_runtime.h>

#define NN 20000
#define EE 50000
#define BB 128
#define HH 64
#define FEATD 28
#define NTYPES 100
#define EDIM 5
#define MPI 3
#define S2S 4

#define TE 128                       // edges/nodes per GEMM tile
#define EDGETILES (EE / TE + EDIM)   // 395
#define ROOTTILES ((NN + TE - 1) / TE)  // 157
#define GRIDMP (ROOTTILES + EDGETILES)  // 552 (fits one resident wave)
#define ZTOT (NN * HH / 4)           // float4 count of one h buffer
#define SMAX 160                     // cached h rows per graph in k_s2s_all
#define SA 512                       // smem softmax-weight slots per graph
#define SCB ((EE + 255) / 256)       // scatter blocks in fused front kernel

typedef unsigned long long u64;

// ---------------- scratch (device globals; no allocation allowed) ----------
__device__ float g_hA[NN * HH];
__device__ float g_hB[NN * HH];
__device__ float g_hC[NN * HH];
__device__ float g_Wmat[EDIM * HH * HH];
__device__ float g_WihT[2 * HH * 4 * HH];   // [128][256] transposed W_ih
__device__ float g_WhhT[HH * 4 * HH];       // [64][256]  transposed W_hh
__device__ float g_a[NN];                   // softmax spill (len > SA only)
__device__ int   g_seg[BB + 1];
__device__ int   g_tcnt[EDIM];
__device__ int   g_tptr[EDIM];
__device__ int   g_toff[EDIM + 1];
__device__ int   g_tileoff[EDIM + 1];
__device__ int   g_psrc[EE];
__device__ int   g_pdst[EE];
__device__ int   g_done = 0;
__device__ unsigned g_barcnt = 0;           // persistent-grid barrier counter

__device__ __forceinline__ float* hsel(int id) {
    return id == 0 ? g_hA : (id == 1 ? g_hB : g_hC);
}

__device__ __forceinline__ void red_v4(float* p, float a, float b, float c, float d) {
    asm volatile("red.global.add.v4.f32 [%0], {%1, %2, %3, %4};"
                 :: "l"(p), "f"(a), "f"(b), "f"(c), "f"(d) : "memory");
}

__device__ __forceinline__ u64 pack2(float x) {
    u64 r; asm("mov.b64 %0, {%1, %1};" : "=l"(r) : "f"(x)); return r;
}
__device__ __forceinline__ void fma2(u64& d, u64 a, u64 b) {
    asm("fma.rn.f32x2 %0, %1, %2, %0;" : "+l"(d) : "l"(a), "l"(b));
}
__device__ __forceinline__ float2 unpack2(u64 v) {
    float2 f; asm("mov.b64 {%0, %1}, %2;" : "=f"(f.x), "=f"(f.y) : "l"(v));
    return f;
}

// device-wide barrier: all GRIDMP blocks resident (one wave) by construction.
__device__ __forceinline__ void grid_bar(unsigned target) {
    __syncthreads();
    if (threadIdx.x == 0) {
        __threadfence();
        atomicAdd(&g_barcnt, 1u);
        while (*((volatile unsigned*)&g_barcnt) < target) {}
        __threadfence();
    }
    __syncthreads();
}

// ======== setup: seg bounds + type hist + (last block) scan ================
__global__ void k_setup(const int* __restrict__ batch,
                        const int* __restrict__ etype) {
    __shared__ int sh[EDIM];
    int tid = threadIdx.x;
    int gid = blockIdx.x * blockDim.x + tid;

    if (tid < EDIM) sh[tid] = 0;

    if (blockIdx.x == 0 && tid <= BB) {
        if (tid == BB) g_seg[BB] = NN;
        else {
            int lo = 0, hi = NN;
            while (lo < hi) {
                int mid = (lo + hi) >> 1;
                if (batch[mid] < tid) lo = mid + 1; else hi = mid;
            }
            g_seg[tid] = lo;
        }
    }
    __syncthreads();

    if (gid < EE) atomicAdd(&sh[etype[gid]], 1);
    __syncthreads();
    if (tid < EDIM) atomicAdd(&g_tcnt[tid], sh[tid]);
    __syncthreads();

    if (tid == 0) {
        __threadfence();
        int old = atomicAdd(&g_done, 1);
        if (old == (int)gridDim.x - 1) {
            int off = 0, toff = 0;
            for (int t = 0; t < EDIM; t++) {
                int n = atomicAdd(&g_tcnt[t], 0);
                g_toff[t] = off;
                g_tileoff[t] = toff;
                g_tptr[t] = off;
                off += n;
                toff += (n + TE - 1) / TE;
                g_tcnt[t] = 0;
            }
            g_toff[EDIM] = off;
            g_tileoff[EDIM] = toff;
            g_done = 0;
            g_barcnt = 0;              // reset persistent barrier for this replay
        }
    }
}

// ======== fused front: scatter + wmat + weight transposes + embedding ======
__global__ void k_front(const int* __restrict__ etype,
                        const int* __restrict__ src,
                        const int* __restrict__ dst,
                        const float* __restrict__ W_e1,
                        const float* __restrict__ b_e1,
                        const float* __restrict__ W_e2,
                        const float* __restrict__ b_e2,
                        const float* __restrict__ feat,
                        const int* __restrict__ ntype,
                        const float* __restrict__ W_emb,
                        const float* __restrict__ b_emb,
                        const float* __restrict__ W_ih,
                        const float* __restrict__ W_hh) {
    int tid = threadIdx.x;
    if (blockIdx.x < SCB) {
        __shared__ int cnt[EDIM];
        __shared__ int basep[EDIM];
        int e = blockIdx.x * 256 + tid;
        int t = (e < EE) ? etype[e] : -1;
        if (tid < EDIM) cnt[tid] = 0;
        __syncthreads();
        int loc = 0;
        if (t >= 0) loc = atomicAdd(&cnt[t], 1);
        __syncthreads();
        if (tid < EDIM && cnt[tid] > 0)
            basep[tid] = atomicAdd(&g_tptr[tid], cnt[tid]);
        __syncthreads();
        if (t >= 0) {
            int pos = basep[t] + loc;
            g_psrc[pos] = src[e];
            g_pdst[pos] = dst[e];
        }
    } else if (blockIdx.x < SCB + 64) {
        __shared__ float hr[EDIM][HH];
        __shared__ float part[4][EDIM][HH];
        int wb = blockIdx.x - SCB;
        if (tid < HH) {
#pragma unroll
            for (int t = 0; t < EDIM; t++)
                hr[t][tid] = fmaxf(W_e1[t * HH + tid] + b_e1[tid], 0.f);
        }
        __syncthreads();
        int jc = tid >> 6;
        int c = tid & 63;
        int idx = wb * 64 + c;
        float a0 = 0.f, a1 = 0.f, a2 = 0.f, a3 = 0.f, a4 = 0.f;
#pragma unroll
        for (int jj = 0; jj < 16; jj++) {
            int j = jc * 16 + jj;
            float w = W_e2[j * (HH * HH) + idx];
            a0 += hr[0][j] * w;
            a1 += hr[1][j] * w;
            a2 += hr[2][j] * w;
            a3 += hr[3][j] * w;
            a4 += hr[4][j] * w;
        }
        part[jc][0][c] = a0; part[jc][1][c] = a1; part[jc][2][c] = a2;
        part[jc][3][c] = a3; part[jc][4][c] = a4;
        __syncthreads();
        if (jc == 0) {
            float bb = b_e2[idx];
#pragma unroll
            for (int t = 0; t < EDIM; t++)
                g_Wmat[t * HH * HH + idx] =
                    bb + part[0][t][c] + part[1][t][c] + part[2][t][c] + part[3][t][c];
        }
    } else if (blockIdx.x < SCB + 65) {
        for (int idx = tid; idx < 2 * HH * 4 * HH; idx += 256) {
            int k = idx >> 8;
            int j = idx & 255;
            g_WihT[idx] = W_ih[j * (2 * HH) + k];
        }
    } else if (blockIdx.x < SCB + 66) {
        for (int idx = tid; idx < HH * 4 * HH; idx += 256) {
            int k = idx >> 8;
            int j = idx & 255;
            g_WhhT[idx] = W_hh[j * HH + k];
        }
    } else {
        __shared__ float sf[4][FEATD];
        int blk = blockIdx.x - SCB - 66;      // 0..4999
        int l = tid >> 6;
        int o = tid & 63;
        int node = blk * 4 + l;
        g_hB[blk * 256 + tid] = 0.f;
        if (o < FEATD) sf[l][o] = feat[node * FEATD + o];
        __syncthreads();
        int t = ntype[node];
        float acc = b_emb[o] + W_emb[t * HH + o];
#pragma unroll
        for (int f = 0; f < FEATD; f++)
            acc += sf[l][f] * W_emb[(NTYPES + f) * HH + o];
        g_hA[node * HH + o] = acc;
    }
}

// ======== persistent MP: all 3 iterations in one launch, grid barriers =====
// TE=128 (proven best). 552 blocks co-resident (smem 36KB -> 6/SM; regs
// capped at 128 by launch_bounds(128,4) -> 4/SM x 148 = 592 >= 552).
// Tile metadata loaded once; per iteration: zero-slice, gather, FMA2 GEMM,
// vector-RED scatter, device barrier.
__global__ __launch_bounds__(128, 4) void k_mp_all(const float* __restrict__ roots,
                                                   const float* __restrict__ bias) {
    int tid = threadIdx.x;

    __shared__ __align__(16) float hsT[HH][TE + 8];   // [k][row]
    __shared__ int sdst[TE];
    __shared__ int ssrc[TE];

    bool is_root = blockIdx.x < (unsigned)ROOTTILES;
    bool active = true;
    const float* Wedge = g_Wmat;   // resolved below for edge tiles
    int base = 0;

    if (is_root) {
        base = blockIdx.x * TE;
        if (tid < TE) {
            int node = base + tid;
            bool ok = node < NN;
            sdst[tid] = ok ? node : -1;
            ssrc[tid] = ok ? node : 0;
        }
    } else {
        int tb = blockIdx.x - ROOTTILES;
        if (tb >= g_tileoff[EDIM]) {
            active = false;
        } else {
            int t = 0;
            while (tb >= g_tileoff[t + 1]) t++;
            base = g_toff[t] + (tb - g_tileoff[t]) * TE;
            int hi = g_toff[t + 1];
            Wedge = g_Wmat + t * HH * HH;
            if (tid < TE) {
                int p = base + tid;
                bool ok = p < hi;
                sdst[tid] = ok ? g_pdst[p] : -1;
                ssrc[tid] = ok ? g_psrc[p] : 0;
            }
        }
    }
    __syncthreads();

    const int ins[3]   = {0, 1, 2};
    const int outs[3]  = {1, 2, 0};
    const int zeros[3] = {2, 0, -1};

#pragma unroll 1
    for (int iter = 0; iter < MPI; iter++) {
        const float* hin = hsel(ins[iter]);
        float* hout      = hsel(outs[iter]);

        // zero slice of next buffer (all blocks, incl. inactive)
        if (zeros[iter] >= 0) {
            float4* z = (float4*)hsel(zeros[iter]);
            const int chunk = (ZTOT + GRIDMP - 1) / GRIDMP;
            int lo = blockIdx.x * chunk;
            int hiz = lo + chunk; if (hiz > ZTOT) hiz = ZTOT;
            for (int i = lo + tid; i < hiz; i += 128)
                z[i] = make_float4(0.f, 0.f, 0.f, 0.f);
        }

        if (active) {
            const float* W = is_root ? (roots + iter * HH * HH) : Wedge;

            // cooperative gather: 4 threads per row, 32 rows/pass, 4 passes
            {
                int q = tid & 3;
                int er = tid >> 2;
#pragma unroll
                for (int pass = 0; pass < 4; pass++) {
                    int e = pass * 32 + er;
                    int s = ssrc[e];
                    const float4* hr = (const float4*)(hin + s * HH + q * 16);
#pragma unroll
                    for (int j = 0; j < 4; j++) {
                        float4 v = hr[j];
                        int k = q * 16 + j * 4;
                        hsT[k + 0][e] = v.x;
                        hsT[k + 1][e] = v.y;
                        hsT[k + 2][e] = v.z;
                        hsT[k + 3][e] = v.w;
                    }
                }
            }
            __syncthreads();

            int rg = tid >> 3;   // 0..15 row group (8 rows = 4 row-pairs)
            int og = tid & 7;    // 0..7  out group (8 outs)

            u64 acc2[4][8];
            if (is_root) {
                float4 b0 = *(const float4*)(bias + iter * HH + og * 8);
                float4 b1 = *(const float4*)(bias + iter * HH + og * 8 + 4);
                float bb[8] = {b0.x, b0.y, b0.z, b0.w, b1.x, b1.y, b1.z, b1.w};
#pragma unroll
                for (int ap = 0; ap < 4; ap++)
#pragma unroll
                    for (int b = 0; b < 8; b++) acc2[ap][b] = pack2(bb[b]);
            } else {
#pragma unroll
                for (int ap = 0; ap < 4; ap++)
#pragma unroll
                    for (int b = 0; b < 8; b++) acc2[ap][b] = 0ull;
            }

            const float4* Wv = (const float4*)(W + og * 8);

#pragma unroll 4
            for (int k = 0; k < HH; k++) {
                double2 ha = *(const double2*)&hsT[k][rg * 8];
                double2 hb = *(const double2*)&hsT[k][rg * 8 + 4];
                u64 h0 = __double_as_longlong(ha.x);
                u64 h1 = __double_as_longlong(ha.y);
                u64 h2 = __double_as_longlong(hb.x);
                u64 h3 = __double_as_longlong(hb.y);
                float4 w0 = __ldg(Wv + k * 16);
                float4 w1 = __ldg(Wv + k * 16 + 1);
                u64 wb0 = pack2(w0.x), wb1 = pack2(w0.y), wb2 = pack2(w0.z), wb3 = pack2(w0.w);
                u64 wb4 = pack2(w1.x), wb5 = pack2(w1.y), wb6 = pack2(w1.z), wb7 = pack2(w1.w);

                fma2(acc2[0][0], h0, wb0); fma2(acc2[0][1], h0, wb1);
                fma2(acc2[0][2], h0, wb2); fma2(acc2[0][3], h0, wb3);
                fma2(acc2[0][4], h0, wb4); fma2(acc2[0][5], h0, wb5);
                fma2(acc2[0][6], h0, wb6); fma2(acc2[0][7], h0, wb7);

                fma2(acc2[1][0], h1, wb0); fma2(acc2[1][1], h1, wb1);
                fma2(acc2[1][2], h1, wb2); fma2(acc2[1][3], h1, wb3);
                fma2(acc2[1][4], h1, wb4); fma2(acc2[1][5], h1, wb5);
                fma2(acc2[1][6], h1, wb6); fma2(acc2[1][7], h1, wb7);

                fma2(acc2[2][0], h2, wb0); fma2(acc2[2][1], h2, wb1);
                fma2(acc2[2][2], h2, wb2); fma2(acc2[2][3], h2, wb3);
                fma2(acc2[2][4], h2, wb4); fma2(acc2[2][5], h2, wb5);
                fma2(acc2[2][6], h2, wb6); fma2(acc2[2][7], h2, wb7);

                fma2(acc2[3][0], h3, wb0); fma2(acc2[3][1], h3, wb1);
                fma2(acc2[3][2], h3, wb2); fma2(acc2[3][3], h3, wb3);
                fma2(acc2[3][4], h3, wb4); fma2(acc2[3][5], h3, wb5);
                fma2(acc2[3][6], h3, wb6); fma2(acc2[3][7], h3, wb7);
            }

#pragma unroll
            for (int ap = 0; ap < 4; ap++) {
                float2 u0 = unpack2(acc2[ap][0]);
                float2 u1 = unpack2(acc2[ap][1]);
                float2 u2 = unpack2(acc2[ap][2]);
                float2 u3 = unpack2(acc2[ap][3]);
                float2 u4 = unpack2(acc2[ap][4]);
                float2 u5 = unpack2(acc2[ap][5]);
                float2 u6 = unpack2(acc2[ap][6]);
                float2 u7 = unpack2(acc2[ap][7]);
                int dlo = sdst[rg * 8 + 2 * ap];
                int dhi = sdst[rg * 8 + 2 * ap + 1];
                if (dlo >= 0) {
                    float* dr = hout + dlo * HH + og * 8;
                    red_v4(dr,     u0.x, u1.x, u2.x, u3.x);
                    red_v4(dr + 4, u4.x, u5.x, u6.x, u7.x);
                }
                if (dhi >= 0) {
                    float* dr = hout + dhi * HH + og * 8;
                    red_v4(dr,     u0.y, u1.y, u2.y, u3.y);
                    red_v4(dr + 4, u4.y, u5.y, u6.y, u7.y);
                }
            }
        }

        // device-wide barrier between iterations (not after the last)
        if (iter < MPI - 1)
            grid_bar((unsigned)((iter + 1) * GRIDMP));
    }
}

// ======== fully fused Set2Set: 4 iterations + output MLP ===================
__global__ __launch_bounds__(256) void k_s2s_all(const float* __restrict__ b_ih,
                                                 const float* __restrict__ b_hh,
                                                 const float* __restrict__ W_o1,
                                                 const float* __restrict__ b_o1,
                                                 const float* __restrict__ W_o2,
                                                 const float* __restrict__ b_o2,
                                                 float* __restrict__ out) {
    const float* h = g_hA;          // final node states after MPI=3 (A->B->C->A)
    int b = blockIdx.x;
    int tid = threadIdx.x;

    __shared__ float hcache[SMAX * HH];   // 40KB
    __shared__ float sa[SA];
    __shared__ float qs[2 * HH];
    __shared__ float gates[4 * HH];
    __shared__ float q[HH];
    __shared__ float hx_s[HH];
    __shared__ float cx_s[HH];
    __shared__ float red[256];
    __shared__ float r4[4][HH];

    int s = g_seg[b], t = g_seg[b + 1];
    int len = t - s;
    int nc = len < SMAX ? len : SMAX;

    {
        float4* d4 = (float4*)hcache;
        const float4* s4 = (const float4*)(h + s * HH);
        int tot = nc * (HH / 4);
        for (int i = tid; i < tot; i += 256) d4[i] = s4[i];
    }
    if (tid < 2 * HH) qs[tid] = 0.f;
    if (tid < HH) { hx_s[tid] = 0.f; cx_s[tid] = 0.f; }
    __syncthreads();

    float ev[8];   // per-thread scores (supports len <= 2048)

    for (int it = 0; it < S2S; it++) {
        {
            float g0 = b_ih[tid];
            float g1 = b_hh[tid];
#pragma unroll 8
            for (int k = 0; k < 2 * HH; k++) g0 += qs[k] * g_WihT[k * 256 + tid];
#pragma unroll 8
            for (int k = 0; k < HH; k++)     g1 += hx_s[k] * g_WhhT[k * 256 + tid];
            gates[tid] = g0 + g1;
        }
        __syncthreads();
        if (tid < HH) {
            float ig = gates[tid], fg = gates[HH + tid];
            float gg = gates[2 * HH + tid], og = gates[3 * HH + tid];
            float si = 1.f / (1.f + expf(-ig));
            float sf = 1.f / (1.f + expf(-fg));
            float so = 1.f / (1.f + expf(-og));
            float c = sf * cx_s[tid] + si * tanhf(gg);
            cx_s[tid] = c;
            float hx = so * tanhf(c);
            hx_s[tid] = hx;
            q[tid] = hx;
        }
        __syncthreads();

        float lmax = -1e30f;
        const float4* q4 = (const float4*)q;
        {
            int i = 0;
            for (int l = tid; l < len && i < 8; l += 256, i++) {
                const float4* hr = (l < nc) ? (const float4*)&hcache[l * HH]
                                            : (const float4*)(h + (s + l) * HH);
                float e = 0.f;
#pragma unroll
                for (int k = 0; k < HH / 4; k++) {
                    float4 hv = hr[k];
                    float4 qv = q4[k];
                    e += hv.x * qv.x + hv.y * qv.y + hv.z * qv.z + hv.w * qv.w;
                }
                ev[i] = e;
                lmax = fmaxf(lmax, e);
            }
        }
        red[tid] = lmax; __syncthreads();
        for (int w = 128; w > 0; w >>= 1) {
            if (tid < w) red[tid] = fmaxf(red[tid], red[tid + w]);
            __syncthreads();
        }
        float m = red[0];
        __syncthreads();

        float lsum = 0.f;
        {
            int i = 0;
            for (int l = tid; l < len && i < 8; l += 256, i++) {
                float a = expf(ev[i] - m);
                if (l < SA) sa[l] = a; else g_a[s + l] = a;
                lsum += a;
            }
        }
        red[tid] = lsum; __syncthreads();
        for (int w = 128; w > 0; w >>= 1) {
            if (tid < w) red[tid] += red[tid + w];
            __syncthreads();
        }
        float denom = red[0];
        if (denom == 0.f) denom = 1.f;
        __syncthreads();

        {
            int part = tid >> 6;
            int o = tid & 63;
            float r = 0.f;
            for (int l = part; l < len; l += 4) {
                float av = (l < SA) ? sa[l] : g_a[s + l];
                float hv = (l < nc) ? hcache[l * HH + o] : h[(s + l) * HH + o];
                r += av * hv;
            }
            r4[part][o] = r;
        }
        __syncthreads();
        if (tid < HH) {
            float r = (r4[0][tid] + r4[1][tid] + r4[2][tid] + r4[3][tid]) / denom;
            qs[tid]      = q[tid];
            qs[HH + tid] = r;
        }
        __syncthreads();
    }

    if (tid < HH) {
        float v = b_o1[tid];
#pragma unroll 8
        for (int k = 0; k < 2 * HH; k++) v += qs[k] * W_o1[k * HH + tid];
        v = fmaxf(v, 0.f);
        red[tid] = v * W_o2[tid];
    }
    __syncthreads();
    for (int w = 32; w > 0; w >>= 1) {
        if (tid < w) red[tid] += red[tid + w];
        __syncthreads();
    }
    if (tid == 0) out[b] = red[0] + b_o2[0];
}

// ---------------------------------------------------------------------------
extern "C" void kernel_launch(void* const* d_in, const int* in_sizes, int n_in,
                              void* d_out, int out_size) {
    const float* node_feat = (const float*)d_in[0];
    const int*   node_type = (const int*)d_in[1];
    const int*   edge_index= (const int*)d_in[2];
    const int*   etype     = (const int*)d_in[3];
    const int*   batch     = (const int*)d_in[4];
    const float* W_emb     = (const float*)d_in[5];
    const float* b_emb     = (const float*)d_in[6];
    const float* W_e1      = (const float*)d_in[7];
    const float* b_e1      = (const float*)d_in[8];
    const float* W_e2      = (const float*)d_in[9];
    const float* b_e2      = (const float*)d_in[10];
    const float* roots     = (const float*)d_in[11];
    const float* conv_bias = (const float*)d_in[12];
    const float* W_ih      = (const float*)d_in[13];
    const float* W_hh      = (const float*)d_in[14];
    const float* b_ih      = (const float*)d_in[15];
    const float* b_hh      = (const float*)d_in[16];
    const float* W_o1      = (const float*)d_in[17];
    const float* b_o1      = (const float*)d_in[18];
    const float* W_o2      = (const float*)d_in[19];
    const float* b_o2      = (const float*)d_in[20];
    float* out = (float*)d_out;

    const int* src = edge_index;
    const int* dst = edge_index + EE;

    k_setup<<<(EE + 255) / 256, 256>>>(batch, etype);
    k_front<<<SCB + 66 + NN / 4, 256>>>(etype, src, dst,
                                        W_e1, b_e1, W_e2, b_e2,
                                        node_feat, node_type, W_emb, b_emb,
                                        W_ih, W_hh);

    // persistent MP: all 3 iterations, device-wide barriers between them
    k_mp_all<<<GRIDMP, 128>>>(roots, conv_bias);

    k_s2s_all<<<BB, 256>>>(b_ih, b_hh, W_o1, b_o1, W_o2, b_o2, out);
}

// round 16
// speedup vs baseline: 1.2694x; 1.0552x over previous
#include <cuda_runtime.h>

#define NN 20000
#define EE 50000
#define BB 128
#define HH 64
#define FEATD 28
#define NTYPES 100
#define EDIM 5
#define MPI 3
#define S2S 4

#define TE 128                       // edges/nodes per GEMM tile
#define EDGETILES (EE / TE + EDIM)   // 395
#define ROOTTILES ((NN + TE - 1) / TE)  // 157
#define GRIDMP (ROOTTILES + EDGETILES)  // 552 (fits one resident wave)
#define ZTOT (NN * HH / 4)           // float4 count of one h buffer
#define SMAX 160                     // cached h rows per graph in k_s2s_all
#define SA 512                       // smem softmax-weight slots per graph
#define SCB ((EE + 255) / 256)       // scatter blocks in fused front kernel

typedef unsigned long long u64;

// ---------------- scratch (device globals; no allocation allowed) ----------
__device__ float g_hA[NN * HH];
__device__ float g_hB[NN * HH];
__device__ float g_hC[NN * HH];
__device__ float g_Wmat[EDIM * HH * HH];
__device__ float g_WihT[2 * HH * 4 * HH];   // [128][256] transposed W_ih
__device__ float g_WhhT[HH * 4 * HH];       // [64][256]  transposed W_hh
__device__ float g_a[NN];                   // softmax spill (len > SA only)
__device__ int   g_seg[BB + 1];
__device__ int   g_tcnt[EDIM];
__device__ int   g_tptr[EDIM];
__device__ int   g_toff[EDIM + 1];
__device__ int   g_tileoff[EDIM + 1];
__device__ int   g_psrc[EE];
__device__ int   g_pdst[EE];
__device__ int   g_done = 0;
__device__ unsigned g_barcnt = 0;           // persistent-grid barrier counter

__device__ __forceinline__ float* hsel(int id) {
    return id == 0 ? g_hA : (id == 1 ? g_hB : g_hC);
}

__device__ __forceinline__ void red_v4(float* p, float a, float b, float c, float d) {
    asm volatile("red.global.add.v4.f32 [%0], {%1, %2, %3, %4};"
                 :: "l"(p), "f"(a), "f"(b), "f"(c), "f"(d) : "memory");
}

__device__ __forceinline__ u64 pack2(float x) {
    u64 r; asm("mov.b64 %0, {%1, %1};" : "=l"(r) : "f"(x)); return r;
}
__device__ __forceinline__ void fma2(u64& d, u64 a, u64 b) {
    asm("fma.rn.f32x2 %0, %1, %2, %0;" : "+l"(d) : "l"(a), "l"(b));
}
__device__ __forceinline__ float2 unpack2(u64 v) {
    float2 f; asm("mov.b64 {%0, %1}, %2;" : "=f"(f.x), "=f"(f.y) : "l"(v));
    return f;
}

__device__ __forceinline__ float warp_max(float v) {
#pragma unroll
    for (int o = 16; o > 0; o >>= 1)
        v = fmaxf(v, __shfl_xor_sync(0xffffffffu, v, o));
    return v;
}
__device__ __forceinline__ float warp_sum(float v) {
#pragma unroll
    for (int o = 16; o > 0; o >>= 1)
        v += __shfl_xor_sync(0xffffffffu, v, o);
    return v;
}

// device-wide barrier: all GRIDMP blocks resident (one wave) by construction.
__device__ __forceinline__ void grid_bar(unsigned target) {
    __syncthreads();
    if (threadIdx.x == 0) {
        __threadfence();
        atomicAdd(&g_barcnt, 1u);
        while (*((volatile unsigned*)&g_barcnt) < target) {}
        __threadfence();
    }
    __syncthreads();
}

// ======== setup: seg bounds + type hist + (last block) scan ================
__global__ void k_setup(const int* __restrict__ batch,
                        const int* __restrict__ etype) {
    __shared__ int sh[EDIM];
    int tid = threadIdx.x;
    int gid = blockIdx.x * blockDim.x + tid;

    if (tid < EDIM) sh[tid] = 0;

    if (blockIdx.x == 0 && tid <= BB) {
        if (tid == BB) g_seg[BB] = NN;
        else {
            int lo = 0, hi = NN;
            while (lo < hi) {
                int mid = (lo + hi) >> 1;
                if (batch[mid] < tid) lo = mid + 1; else hi = mid;
            }
            g_seg[tid] = lo;
        }
    }
    __syncthreads();

    if (gid < EE) atomicAdd(&sh[etype[gid]], 1);
    __syncthreads();
    if (tid < EDIM) atomicAdd(&g_tcnt[tid], sh[tid]);
    __syncthreads();

    if (tid == 0) {
        __threadfence();
        int old = atomicAdd(&g_done, 1);
        if (old == (int)gridDim.x - 1) {
            int off = 0, toff = 0;
            for (int t = 0; t < EDIM; t++) {
                int n = atomicAdd(&g_tcnt[t], 0);
                g_toff[t] = off;
                g_tileoff[t] = toff;
                g_tptr[t] = off;
                off += n;
                toff += (n + TE - 1) / TE;
                g_tcnt[t] = 0;
            }
            g_toff[EDIM] = off;
            g_tileoff[EDIM] = toff;
            g_done = 0;
            g_barcnt = 0;              // reset persistent barrier for this replay
        }
    }
}

// ======== fused front: scatter + wmat + weight transposes + embedding ======
__global__ void k_front(const int* __restrict__ etype,
                        const int* __restrict__ src,
                        const int* __restrict__ dst,
                        const float* __restrict__ W_e1,
                        const float* __restrict__ b_e1,
                        const float* __restrict__ W_e2,
                        const float* __restrict__ b_e2,
                        const float* __restrict__ feat,
                        const int* __restrict__ ntype,
                        const float* __restrict__ W_emb,
                        const float* __restrict__ b_emb,
                        const float* __restrict__ W_ih,
                        const float* __restrict__ W_hh) {
    int tid = threadIdx.x;
    if (blockIdx.x < SCB) {
        __shared__ int cnt[EDIM];
        __shared__ int basep[EDIM];
        int e = blockIdx.x * 256 + tid;
        int t = (e < EE) ? etype[e] : -1;
        if (tid < EDIM) cnt[tid] = 0;
        __syncthreads();
        int loc = 0;
        if (t >= 0) loc = atomicAdd(&cnt[t], 1);
        __syncthreads();
        if (tid < EDIM && cnt[tid] > 0)
            basep[tid] = atomicAdd(&g_tptr[tid], cnt[tid]);
        __syncthreads();
        if (t >= 0) {
            int pos = basep[t] + loc;
            g_psrc[pos] = src[e];
            g_pdst[pos] = dst[e];
        }
    } else if (blockIdx.x < SCB + 64) {
        __shared__ float hr[EDIM][HH];
        __shared__ float part[4][EDIM][HH];
        int wb = blockIdx.x - SCB;
        if (tid < HH) {
#pragma unroll
            for (int t = 0; t < EDIM; t++)
                hr[t][tid] = fmaxf(W_e1[t * HH + tid] + b_e1[tid], 0.f);
        }
        __syncthreads();
        int jc = tid >> 6;
        int c = tid & 63;
        int idx = wb * 64 + c;
        float a0 = 0.f, a1 = 0.f, a2 = 0.f, a3 = 0.f, a4 = 0.f;
#pragma unroll
        for (int jj = 0; jj < 16; jj++) {
            int j = jc * 16 + jj;
            float w = W_e2[j * (HH * HH) + idx];
            a0 += hr[0][j] * w;
            a1 += hr[1][j] * w;
            a2 += hr[2][j] * w;
            a3 += hr[3][j] * w;
            a4 += hr[4][j] * w;
        }
        part[jc][0][c] = a0; part[jc][1][c] = a1; part[jc][2][c] = a2;
        part[jc][3][c] = a3; part[jc][4][c] = a4;
        __syncthreads();
        if (jc == 0) {
            float bb = b_e2[idx];
#pragma unroll
            for (int t = 0; t < EDIM; t++)
                g_Wmat[t * HH * HH + idx] =
                    bb + part[0][t][c] + part[1][t][c] + part[2][t][c] + part[3][t][c];
        }
    } else if (blockIdx.x < SCB + 65) {
        for (int idx = tid; idx < 2 * HH * 4 * HH; idx += 256) {
            int k = idx >> 8;
            int j = idx & 255;
            g_WihT[idx] = W_ih[j * (2 * HH) + k];
        }
    } else if (blockIdx.x < SCB + 66) {
        for (int idx = tid; idx < HH * 4 * HH; idx += 256) {
            int k = idx >> 8;
            int j = idx & 255;
            g_WhhT[idx] = W_hh[j * HH + k];
        }
    } else {
        __shared__ float sf[4][FEATD];
        int blk = blockIdx.x - SCB - 66;      // 0..4999
        int l = tid >> 6;
        int o = tid & 63;
        int node = blk * 4 + l;
        g_hB[blk * 256 + tid] = 0.f;
        if (o < FEATD) sf[l][o] = feat[node * FEATD + o];
        __syncthreads();
        int t = ntype[node];
        float acc = b_emb[o] + W_emb[t * HH + o];
#pragma unroll
        for (int f = 0; f < FEATD; f++)
            acc += sf[l][f] * W_emb[(NTYPES + f) * HH + o];
        g_hA[node * HH + o] = acc;
    }
}

// ======== persistent MP: all 3 iterations in one launch, grid barriers =====
__global__ __launch_bounds__(128, 4) void k_mp_all(const float* __restrict__ roots,
                                                   const float* __restrict__ bias) {
    int tid = threadIdx.x;

    __shared__ __align__(16) float hsT[HH][TE + 8];   // [k][row]
    __shared__ int sdst[TE];
    __shared__ int ssrc[TE];

    bool is_root = blockIdx.x < (unsigned)ROOTTILES;
    bool active = true;
    const float* Wedge = g_Wmat;
    int base = 0;

    if (is_root) {
        base = blockIdx.x * TE;
        if (tid < TE) {
            int node = base + tid;
            bool ok = node < NN;
            sdst[tid] = ok ? node : -1;
            ssrc[tid] = ok ? node : 0;
        }
    } else {
        int tb = blockIdx.x - ROOTTILES;
        if (tb >= g_tileoff[EDIM]) {
            active = false;
        } else {
            int t = 0;
            while (tb >= g_tileoff[t + 1]) t++;
            base = g_toff[t] + (tb - g_tileoff[t]) * TE;
            int hi = g_toff[t + 1];
            Wedge = g_Wmat + t * HH * HH;
            if (tid < TE) {
                int p = base + tid;
                bool ok = p < hi;
                sdst[tid] = ok ? g_pdst[p] : -1;
                ssrc[tid] = ok ? g_psrc[p] : 0;
            }
        }
    }
    __syncthreads();

    const int ins[3]   = {0, 1, 2};
    const int outs[3]  = {1, 2, 0};
    const int zeros[3] = {2, 0, -1};

#pragma unroll 1
    for (int iter = 0; iter < MPI; iter++) {
        const float* hin = hsel(ins[iter]);
        float* hout      = hsel(outs[iter]);

        if (zeros[iter] >= 0) {
            float4* z = (float4*)hsel(zeros[iter]);
            const int chunk = (ZTOT + GRIDMP - 1) / GRIDMP;
            int lo = blockIdx.x * chunk;
            int hiz = lo + chunk; if (hiz > ZTOT) hiz = ZTOT;
            for (int i = lo + tid; i < hiz; i += 128)
                z[i] = make_float4(0.f, 0.f, 0.f, 0.f);
        }

        if (active) {
            const float* W = is_root ? (roots + iter * HH * HH) : Wedge;

            {
                int q = tid & 3;
                int er = tid >> 2;
#pragma unroll
                for (int pass = 0; pass < 4; pass++) {
                    int e = pass * 32 + er;
                    int s = ssrc[e];
                    const float4* hr = (const float4*)(hin + s * HH + q * 16);
#pragma unroll
                    for (int j = 0; j < 4; j++) {
                        float4 v = hr[j];
                        int k = q * 16 + j * 4;
                        hsT[k + 0][e] = v.x;
                        hsT[k + 1][e] = v.y;
                        hsT[k + 2][e] = v.z;
                        hsT[k + 3][e] = v.w;
                    }
                }
            }
            __syncthreads();

            int rg = tid >> 3;
            int og = tid & 7;

            u64 acc2[4][8];
            if (is_root) {
                float4 b0 = *(const float4*)(bias + iter * HH + og * 8);
                float4 b1 = *(const float4*)(bias + iter * HH + og * 8 + 4);
                float bb[8] = {b0.x, b0.y, b0.z, b0.w, b1.x, b1.y, b1.z, b1.w};
#pragma unroll
                for (int ap = 0; ap < 4; ap++)
#pragma unroll
                    for (int b = 0; b < 8; b++) acc2[ap][b] = pack2(bb[b]);
            } else {
#pragma unroll
                for (int ap = 0; ap < 4; ap++)
#pragma unroll
                    for (int b = 0; b < 8; b++) acc2[ap][b] = 0ull;
            }

            const float4* Wv = (const float4*)(W + og * 8);

#pragma unroll 4
            for (int k = 0; k < HH; k++) {
                double2 ha = *(const double2*)&hsT[k][rg * 8];
                double2 hb = *(const double2*)&hsT[k][rg * 8 + 4];
                u64 h0 = __double_as_longlong(ha.x);
                u64 h1 = __double_as_longlong(ha.y);
                u64 h2 = __double_as_longlong(hb.x);
                u64 h3 = __double_as_longlong(hb.y);
                float4 w0 = __ldg(Wv + k * 16);
                float4 w1 = __ldg(Wv + k * 16 + 1);
                u64 wb0 = pack2(w0.x), wb1 = pack2(w0.y), wb2 = pack2(w0.z), wb3 = pack2(w0.w);
                u64 wb4 = pack2(w1.x), wb5 = pack2(w1.y), wb6 = pack2(w1.z), wb7 = pack2(w1.w);

                fma2(acc2[0][0], h0, wb0); fma2(acc2[0][1], h0, wb1);
                fma2(acc2[0][2], h0, wb2); fma2(acc2[0][3], h0, wb3);
                fma2(acc2[0][4], h0, wb4); fma2(acc2[0][5], h0, wb5);
                fma2(acc2[0][6], h0, wb6); fma2(acc2[0][7], h0, wb7);

                fma2(acc2[1][0], h1, wb0); fma2(acc2[1][1], h1, wb1);
                fma2(acc2[1][2], h1, wb2); fma2(acc2[1][3], h1, wb3);
                fma2(acc2[1][4], h1, wb4); fma2(acc2[1][5], h1, wb5);
                fma2(acc2[1][6], h1, wb6); fma2(acc2[1][7], h1, wb7);

                fma2(acc2[2][0], h2, wb0); fma2(acc2[2][1], h2, wb1);
                fma2(acc2[2][2], h2, wb2); fma2(acc2[2][3], h2, wb3);
                fma2(acc2[2][4], h2, wb4); fma2(acc2[2][5], h2, wb5);
                fma2(acc2[2][6], h2, wb6); fma2(acc2[2][7], h2, wb7);

                fma2(acc2[3][0], h3, wb0); fma2(acc2[3][1], h3, wb1);
                fma2(acc2[3][2], h3, wb2); fma2(acc2[3][3], h3, wb3);
                fma2(acc2[3][4], h3, wb4); fma2(acc2[3][5], h3, wb5);
                fma2(acc2[3][6], h3, wb6); fma2(acc2[3][7], h3, wb7);
            }

#pragma unroll
            for (int ap = 0; ap < 4; ap++) {
                float2 u0 = unpack2(acc2[ap][0]);
                float2 u1 = unpack2(acc2[ap][1]);
                float2 u2 = unpack2(acc2[ap][2]);
                float2 u3 = unpack2(acc2[ap][3]);
                float2 u4 = unpack2(acc2[ap][4]);
                float2 u5 = unpack2(acc2[ap][5]);
                float2 u6 = unpack2(acc2[ap][6]);
                float2 u7 = unpack2(acc2[ap][7]);
                int dlo = sdst[rg * 8 + 2 * ap];
                int dhi = sdst[rg * 8 + 2 * ap + 1];
                if (dlo >= 0) {
                    float* dr = hout + dlo * HH + og * 8;
                    red_v4(dr,     u0.x, u1.x, u2.x, u3.x);
                    red_v4(dr + 4, u4.x, u5.x, u6.x, u7.x);
                }
                if (dhi >= 0) {
                    float* dr = hout + dhi * HH + og * 8;
                    red_v4(dr,     u0.y, u1.y, u2.y, u3.y);
                    red_v4(dr + 4, u4.y, u5.y, u6.y, u7.y);
                }
            }
        }

        if (iter < MPI - 1)
            grid_bar((unsigned)((iter + 1) * GRIDMP));
    }
}

// ======== fully fused Set2Set: 4 iterations + output MLP ===================
// Latency-optimized: unroll-16 dual-acc gate loops (no launch_bounds reg cap),
// register-resident scores via fully unrolled predicate loops, warp-shuffle
// reductions (2 bars instead of 9 per reduction).
__global__ void k_s2s_all(const float* __restrict__ b_ih,
                          const float* __restrict__ b_hh,
                          const float* __restrict__ W_o1,
                          const float* __restrict__ b_o1,
                          const float* __restrict__ W_o2,
                          const float* __restrict__ b_o2,
                          float* __restrict__ out) {
    const float* h = g_hA;          // final node states after MPI=3 (A->B->C->A)
    int b = blockIdx.x;
    int tid = threadIdx.x;
    int lane = tid & 31;
    int wid = tid >> 5;             // 0..7

    __shared__ float hcache[SMAX * HH];   // 40KB
    __shared__ float sa[SA];
    __shared__ float qs[2 * HH];
    __shared__ float gates[4 * HH];
    __shared__ float q[HH];
    __shared__ float hx_s[HH];
    __shared__ float cx_s[HH];
    __shared__ float red[8];
    __shared__ float r4[4][HH];

    int s = g_seg[b], t = g_seg[b + 1];
    int len = t - s;
    int nc = len < SMAX ? len : SMAX;

    {
        float4* d4 = (float4*)hcache;
        const float4* s4 = (const float4*)(h + s * HH);
        int tot = nc * (HH / 4);
        for (int i = tid; i < tot; i += 256) d4[i] = s4[i];
    }
    if (tid < 2 * HH) qs[tid] = 0.f;
    if (tid < HH) { hx_s[tid] = 0.f; cx_s[tid] = 0.f; }
    __syncthreads();

    float ev0, ev1, ev2, ev3, ev4, ev5, ev6, ev7;   // register scores (len<=2048)

    for (int it = 0; it < S2S; it++) {
        // ---- LSTM gates: unroll 16, dual accumulators for MLP ----
        {
            float ga = b_ih[tid], gb = b_hh[tid];
#pragma unroll 16
            for (int k = 0; k < 2 * HH; k += 2) {
                ga += qs[k]     * g_WihT[k * 256 + tid];
                gb += qs[k + 1] * g_WihT[(k + 1) * 256 + tid];
            }
#pragma unroll 16
            for (int k = 0; k < HH; k += 2) {
                ga += hx_s[k]     * g_WhhT[k * 256 + tid];
                gb += hx_s[k + 1] * g_WhhT[(k + 1) * 256 + tid];
            }
            gates[tid] = ga + gb;
        }
        __syncthreads();
        if (tid < HH) {
            float ig = gates[tid], fg = gates[HH + tid];
            float gg = gates[2 * HH + tid], og = gates[3 * HH + tid];
            float si = 1.f / (1.f + expf(-ig));
            float sf = 1.f / (1.f + expf(-fg));
            float so = 1.f / (1.f + expf(-og));
            float c = sf * cx_s[tid] + si * tanhf(gg);
            cx_s[tid] = c;
            float hx = so * tanhf(c);
            hx_s[tid] = hx;
            q[tid] = hx;
        }
        __syncthreads();

        // ---- pass 1: e = <h, q>, max (registers, fixed unroll) ----
        float lmax = -1e30f;
        const float4* q4 = (const float4*)q;
#define S2S_SCORE(EV, I)                                                      \
        {                                                                     \
            int l = tid + (I) * 256;                                          \
            if (l < len) {                                                    \
                const float4* hr = (l < nc) ? (const float4*)&hcache[l * HH]  \
                                            : (const float4*)(h + (s + l) * HH); \
                float e = 0.f;                                                \
                _Pragma("unroll")                                             \
                for (int k = 0; k < HH / 4; k++) {                            \
                    float4 hv = hr[k];                                        \
                    float4 qv = q4[k];                                        \
                    e += hv.x * qv.x + hv.y * qv.y + hv.z * qv.z + hv.w * qv.w; \
                }                                                             \
                EV = e;                                                       \
                lmax = fmaxf(lmax, e);                                        \
            }                                                                 \
        }
        S2S_SCORE(ev0, 0) S2S_SCORE(ev1, 1) S2S_SCORE(ev2, 2) S2S_SCORE(ev3, 3)
        S2S_SCORE(ev4, 4) S2S_SCORE(ev5, 5) S2S_SCORE(ev6, 6) S2S_SCORE(ev7, 7)
#undef S2S_SCORE

        // warp-shuffle max reduction (2 bars)
        lmax = warp_max(lmax);
        if (lane == 0) red[wid] = lmax;
        __syncthreads();
        if (tid < 8) {
            float v = red[tid];
#pragma unroll
            for (int o = 4; o > 0; o >>= 1)
                v = fmaxf(v, __shfl_xor_sync(0xffu, v, o));
            if (tid == 0) red[0] = v;
        }
        __syncthreads();
        float m = red[0];

        // ---- pass 2: a = exp(e - m), sum ----
        float lsum = 0.f;
#define S2S_EXP(EV, I)                                                        \
        {                                                                     \
            int l = tid + (I) * 256;                                          \
            if (l < len) {                                                    \
                float a = expf(EV - m);                                       \
                if (l < SA) sa[l] = a; else g_a[s + l] = a;                   \
                lsum += a;                                                    \
            }                                                                 \
        }
        S2S_EXP(ev0, 0) S2S_EXP(ev1, 1) S2S_EXP(ev2, 2) S2S_EXP(ev3, 3)
        S2S_EXP(ev4, 4) S2S_EXP(ev5, 5) S2S_EXP(ev6, 6) S2S_EXP(ev7, 7)
#undef S2S_EXP

        lsum = warp_sum(lsum);
        if (lane == 0) red[wid] = lsum;
        __syncthreads();
        if (tid < 8) {
            float v = red[tid];
#pragma unroll
            for (int o = 4; o > 0; o >>= 1)
                v += __shfl_xor_sync(0xffu, v, o);
            if (tid == 0) red[0] = v;
        }
        __syncthreads();
        float denom = red[0];
        if (denom == 0.f) denom = 1.f;

        // ---- pass 3: r[o] = sum a*h / denom, 4-way n split, unroll 2 ----
        {
            int part = tid >> 6;
            int o = tid & 63;
            float r0 = 0.f, r1 = 0.f;
            int l = part;
            for (; l + 4 < len; l += 8) {
                float av0 = (l < SA) ? sa[l] : g_a[s + l];
                float hv0 = (l < nc) ? hcache[l * HH + o] : h[(s + l) * HH + o];
                int l2 = l + 4;
                float av1 = (l2 < SA) ? sa[l2] : g_a[s + l2];
                float hv1 = (l2 < nc) ? hcache[l2 * HH + o] : h[(s + l2) * HH + o];
                r0 += av0 * hv0;
                r1 += av1 * hv1;
            }
            if (l < len) {
                float av = (l < SA) ? sa[l] : g_a[s + l];
                float hv = (l < nc) ? hcache[l * HH + o] : h[(s + l) * HH + o];
                r0 += av * hv;
            }
            r4[part][o] = r0 + r1;
        }
        __syncthreads();
        if (tid < HH) {
            float r = (r4[0][tid] + r4[1][tid] + r4[2][tid] + r4[3][tid]) / denom;
            qs[tid]      = q[tid];
            qs[HH + tid] = r;
        }
        __syncthreads();
    }

    // ---- output MLP (warp-shuffle final reduction) ----
    float contrib = 0.f;
    if (tid < HH) {
        float v = b_o1[tid];
#pragma unroll 8
        for (int k = 0; k < 2 * HH; k++) v += qs[k] * W_o1[k * HH + tid];
        v = fmaxf(v, 0.f);
        contrib = v * W_o2[tid];
    }
    if (wid < 2) {
        contrib = warp_sum(contrib);
        if (lane == 0) red[wid] = contrib;
    }
    __syncthreads();
    if (tid == 0) out[b] = red[0] + red[1] + b_o2[0];
}

// ---------------------------------------------------------------------------
extern "C" void kernel_launch(void* const* d_in, const int* in_sizes, int n_in,
                              void* d_out, int out_size) {
    const float* node_feat = (const float*)d_in[0];
    const int*   node_type = (const int*)d_in[1];
    const int*   edge_index= (const int*)d_in[2];
    const int*   etype     = (const int*)d_in[3];
    const int*   batch     = (const int*)d_in[4];
    const float* W_emb     = (const float*)d_in[5];
    const float* b_emb     = (const float*)d_in[6];
    const float* W_e1      = (const float*)d_in[7];
    const float* b_e1      = (const float*)d_in[8];
    const float* W_e2      = (const float*)d_in[9];
    const float* b_e2      = (const float*)d_in[10];
    const float* roots     = (const float*)d_in[11];
    const float* conv_bias = (const float*)d_in[12];
    const float* W_ih      = (const float*)d_in[13];
    const float* W_hh      = (const float*)d_in[14];
    const float* b_ih      = (const float*)d_in[15];
    const float* b_hh      = (const float*)d_in[16];
    const float* W_o1      = (const float*)d_in[17];
    const float* b_o1      = (const float*)d_in[18];
    const float* W_o2      = (const float*)d_in[19];
    const float* b_o2      = (const float*)d_in[20];
    float* out = (float*)d_out;

    const int* src = edge_index;
    const int* dst = edge_index + EE;

    k_setup<<<(EE + 255) / 256, 256>>>(batch, etype);
    k_front<<<SCB + 66 + NN / 4, 256>>>(etype, src, dst,
                                        W_e1, b_e1, W_e2, b_e2,
                                        node_feat, node_type, W_emb, b_emb,
                                        W_ih, W_hh);

    // persistent MP: all 3 iterations, device-wide barriers between them
    k_mp_all<<<GRIDMP, 128>>>(roots, conv_bias);

    k_s2s_all<<<BB, 256>>>(b_ih, b_hh, W_o1, b_o1, W_o2, b_o2, out);
}

// round 17
// speedup vs baseline: 1.3656x; 1.0758x over previous
#include <cuda_runtime.h>

#define NN 20000
#define EE 50000
#define BB 128
#define HH 64
#define FEATD 28
#define NTYPES 100
#define EDIM 5
#define MPI 3
#define S2S 4

#define TE 128                       // edges/nodes per GEMM tile
#define EDGETILES (EE / TE + EDIM)   // 395
#define ROOTTILES ((NN + TE - 1) / TE)  // 157
#define GRIDMP (ROOTTILES + EDGETILES)  // 552 (fits one resident wave)
#define ZTOT (NN * HH / 4)           // float4 count of one h buffer
#define SMAX 160                     // cached h rows per graph in k_s2s_all
#define SA 512                       // smem softmax-weight slots per graph
#define SCB ((EE + 255) / 256)       // scatter blocks in fused front kernel

typedef unsigned long long u64;

// ---------------- scratch (device globals; no allocation allowed) ----------
__device__ float g_hA[NN * HH];
__device__ float g_hB[NN * HH];
__device__ float g_hC[NN * HH];
__device__ float g_Wmat[EDIM * HH * HH];
__device__ float g_WihT[2 * HH * 4 * HH];   // [128][256] transposed W_ih
__device__ float g_WhhT[HH * 4 * HH];       // [64][256]  transposed W_hh
__device__ float g_a[NN];                   // softmax spill (len > SA only)
__device__ int   g_seg[BB + 1];
__device__ int   g_tcnt[EDIM];
__device__ int   g_tptr[EDIM];
__device__ int   g_toff[EDIM + 1];
__device__ int   g_tileoff[EDIM + 1];
__device__ int   g_psrc[EE];
__device__ int   g_pdst[EE];
__device__ int   g_done = 0;
__device__ unsigned g_barcnt = 0;           // persistent-grid barrier counter

__device__ __forceinline__ float* hsel(int id) {
    return id == 0 ? g_hA : (id == 1 ? g_hB : g_hC);
}

__device__ __forceinline__ void red_v4(float* p, float a, float b, float c, float d) {
    asm volatile("red.global.add.v4.f32 [%0], {%1, %2, %3, %4};"
                 :: "l"(p), "f"(a), "f"(b), "f"(c), "f"(d) : "memory");
}

__device__ __forceinline__ u64 pack2(float x) {
    u64 r; asm("mov.b64 %0, {%1, %1};" : "=l"(r) : "f"(x)); return r;
}
__device__ __forceinline__ void fma2(u64& d, u64 a, u64 b) {
    asm("fma.rn.f32x2 %0, %1, %2, %0;" : "+l"(d) : "l"(a), "l"(b));
}
__device__ __forceinline__ float2 unpack2(u64 v) {
    float2 f; asm("mov.b64 {%0, %1}, %2;" : "=f"(f.x), "=f"(f.y) : "l"(v));
    return f;
}

__device__ __forceinline__ float warp_sum(float v) {
#pragma unroll
    for (int o = 16; o > 0; o >>= 1)
        v += __shfl_xor_sync(0xffffffffu, v, o);
    return v;
}

// device-wide barrier: all GRIDMP blocks resident (one wave) by construction.
__device__ __forceinline__ void grid_bar(unsigned target) {
    __syncthreads();
    if (threadIdx.x == 0) {
        __threadfence();
        atomicAdd(&g_barcnt, 1u);
        while (*((volatile unsigned*)&g_barcnt) < target) {}
        __threadfence();
    }
    __syncthreads();
}

// ======== setup: seg bounds + type hist + (last block) scan ================
__global__ void k_setup(const int* __restrict__ batch,
                        const int* __restrict__ etype) {
    __shared__ int sh[EDIM];
    int tid = threadIdx.x;
    int gid = blockIdx.x * blockDim.x + tid;

    if (tid < EDIM) sh[tid] = 0;

    if (blockIdx.x == 0 && tid <= BB) {
        if (tid == BB) g_seg[BB] = NN;
        else {
            int lo = 0, hi = NN;
            while (lo < hi) {
                int mid = (lo + hi) >> 1;
                if (batch[mid] < tid) lo = mid + 1; else hi = mid;
            }
            g_seg[tid] = lo;
        }
    }
    __syncthreads();

    if (gid < EE) atomicAdd(&sh[etype[gid]], 1);
    __syncthreads();
    if (tid < EDIM) atomicAdd(&g_tcnt[tid], sh[tid]);
    __syncthreads();

    if (tid == 0) {
        __threadfence();
        int old = atomicAdd(&g_done, 1);
        if (old == (int)gridDim.x - 1) {
            int off = 0, toff = 0;
            for (int t = 0; t < EDIM; t++) {
                int n = atomicAdd(&g_tcnt[t], 0);
                g_toff[t] = off;
                g_tileoff[t] = toff;
                g_tptr[t] = off;
                off += n;
                toff += (n + TE - 1) / TE;
                g_tcnt[t] = 0;
            }
            g_toff[EDIM] = off;
            g_tileoff[EDIM] = toff;
            g_done = 0;
            g_barcnt = 0;              // reset persistent barrier for this replay
        }
    }
}

// ======== fused front: scatter + wmat + weight transposes + embedding ======
__global__ void k_front(const int* __restrict__ etype,
                        const int* __restrict__ src,
                        const int* __restrict__ dst,
                        const float* __restrict__ W_e1,
                        const float* __restrict__ b_e1,
                        const float* __restrict__ W_e2,
                        const float* __restrict__ b_e2,
                        const float* __restrict__ feat,
                        const int* __restrict__ ntype,
                        const float* __restrict__ W_emb,
                        const float* __restrict__ b_emb,
                        const float* __restrict__ W_ih,
                        const float* __restrict__ W_hh) {
    int tid = threadIdx.x;
    if (blockIdx.x < SCB) {
        __shared__ int cnt[EDIM];
        __shared__ int basep[EDIM];
        int e = blockIdx.x * 256 + tid;
        int t = (e < EE) ? etype[e] : -1;
        if (tid < EDIM) cnt[tid] = 0;
        __syncthreads();
        int loc = 0;
        if (t >= 0) loc = atomicAdd(&cnt[t], 1);
        __syncthreads();
        if (tid < EDIM && cnt[tid] > 0)
            basep[tid] = atomicAdd(&g_tptr[tid], cnt[tid]);
        __syncthreads();
        if (t >= 0) {
            int pos = basep[t] + loc;
            g_psrc[pos] = src[e];
            g_pdst[pos] = dst[e];
        }
    } else if (blockIdx.x < SCB + 64) {
        __shared__ float hr[EDIM][HH];
        __shared__ float part[4][EDIM][HH];
        int wb = blockIdx.x - SCB;
        if (tid < HH) {
#pragma unroll
            for (int t = 0; t < EDIM; t++)
                hr[t][tid] = fmaxf(W_e1[t * HH + tid] + b_e1[tid], 0.f);
        }
        __syncthreads();
        int jc = tid >> 6;
        int c = tid & 63;
        int idx = wb * 64 + c;
        float a0 = 0.f, a1 = 0.f, a2 = 0.f, a3 = 0.f, a4 = 0.f;
#pragma unroll
        for (int jj = 0; jj < 16; jj++) {
            int j = jc * 16 + jj;
            float w = W_e2[j * (HH * HH) + idx];
            a0 += hr[0][j] * w;
            a1 += hr[1][j] * w;
            a2 += hr[2][j] * w;
            a3 += hr[3][j] * w;
            a4 += hr[4][j] * w;
        }
        part[jc][0][c] = a0; part[jc][1][c] = a1; part[jc][2][c] = a2;
        part[jc][3][c] = a3; part[jc][4][c] = a4;
        __syncthreads();
        if (jc == 0) {
            float bb = b_e2[idx];
#pragma unroll
            for (int t = 0; t < EDIM; t++)
                g_Wmat[t * HH * HH + idx] =
                    bb + part[0][t][c] + part[1][t][c] + part[2][t][c] + part[3][t][c];
        }
    } else if (blockIdx.x < SCB + 65) {
        for (int idx = tid; idx < 2 * HH * 4 * HH; idx += 256) {
            int k = idx >> 8;
            int j = idx & 255;
            g_WihT[idx] = W_ih[j * (2 * HH) + k];
        }
    } else if (blockIdx.x < SCB + 66) {
        for (int idx = tid; idx < HH * 4 * HH; idx += 256) {
            int k = idx >> 8;
            int j = idx & 255;
            g_WhhT[idx] = W_hh[j * HH + k];
        }
    } else {
        __shared__ float sf[4][FEATD];
        int blk = blockIdx.x - SCB - 66;      // 0..4999
        int l = tid >> 6;
        int o = tid & 63;
        int node = blk * 4 + l;
        g_hB[blk * 256 + tid] = 0.f;
        if (o < FEATD) sf[l][o] = feat[node * FEATD + o];
        __syncthreads();
        int t = ntype[node];
        float acc = b_emb[o] + W_emb[t * HH + o];
#pragma unroll
        for (int f = 0; f < FEATD; f++)
            acc += sf[l][f] * W_emb[(NTYPES + f) * HH + o];
        g_hA[node * HH + o] = acc;
    }
}

// ======== persistent MP: all 3 iterations in one launch, grid barriers =====
__global__ __launch_bounds__(128, 4) void k_mp_all(const float* __restrict__ roots,
                                                   const float* __restrict__ bias) {
    int tid = threadIdx.x;

    __shared__ __align__(16) float hsT[HH][TE + 8];   // [k][row]
    __shared__ int sdst[TE];
    __shared__ int ssrc[TE];

    bool is_root = blockIdx.x < (unsigned)ROOTTILES;
    bool active = true;
    const float* Wedge = g_Wmat;
    int base = 0;

    if (is_root) {
        base = blockIdx.x * TE;
        if (tid < TE) {
            int node = base + tid;
            bool ok = node < NN;
            sdst[tid] = ok ? node : -1;
            ssrc[tid] = ok ? node : 0;
        }
    } else {
        int tb = blockIdx.x - ROOTTILES;
        if (tb >= g_tileoff[EDIM]) {
            active = false;
        } else {
            int t = 0;
            while (tb >= g_tileoff[t + 1]) t++;
            base = g_toff[t] + (tb - g_tileoff[t]) * TE;
            int hi = g_toff[t + 1];
            Wedge = g_Wmat + t * HH * HH;
            if (tid < TE) {
                int p = base + tid;
                bool ok = p < hi;
                sdst[tid] = ok ? g_pdst[p] : -1;
                ssrc[tid] = ok ? g_psrc[p] : 0;
            }
        }
    }
    __syncthreads();

    const int ins[3]   = {0, 1, 2};
    const int outs[3]  = {1, 2, 0};
    const int zeros[3] = {2, 0, -1};

#pragma unroll 1
    for (int iter = 0; iter < MPI; iter++) {
        const float* hin = hsel(ins[iter]);
        float* hout      = hsel(outs[iter]);

        if (zeros[iter] >= 0) {
            float4* z = (float4*)hsel(zeros[iter]);
            const int chunk = (ZTOT + GRIDMP - 1) / GRIDMP;
            int lo = blockIdx.x * chunk;
            int hiz = lo + chunk; if (hiz > ZTOT) hiz = ZTOT;
            for (int i = lo + tid; i < hiz; i += 128)
                z[i] = make_float4(0.f, 0.f, 0.f, 0.f);
        }

        if (active) {
            const float* W = is_root ? (roots + iter * HH * HH) : Wedge;

            {
                int q = tid & 3;
                int er = tid >> 2;
#pragma unroll
                for (int pass = 0; pass < 4; pass++) {
                    int e = pass * 32 + er;
                    int s = ssrc[e];
                    const float4* hr = (const float4*)(hin + s * HH + q * 16);
#pragma unroll
                    for (int j = 0; j < 4; j++) {
                        float4 v = hr[j];
                        int k = q * 16 + j * 4;
                        hsT[k + 0][e] = v.x;
                        hsT[k + 1][e] = v.y;
                        hsT[k + 2][e] = v.z;
                        hsT[k + 3][e] = v.w;
                    }
                }
            }
            __syncthreads();

            int rg = tid >> 3;
            int og = tid & 7;

            u64 acc2[4][8];
            if (is_root) {
                float4 b0 = *(const float4*)(bias + iter * HH + og * 8);
                float4 b1 = *(const float4*)(bias + iter * HH + og * 8 + 4);
                float bb[8] = {b0.x, b0.y, b0.z, b0.w, b1.x, b1.y, b1.z, b1.w};
#pragma unroll
                for (int ap = 0; ap < 4; ap++)
#pragma unroll
                    for (int b = 0; b < 8; b++) acc2[ap][b] = pack2(bb[b]);
            } else {
#pragma unroll
                for (int ap = 0; ap < 4; ap++)
#pragma unroll
                    for (int b = 0; b < 8; b++) acc2[ap][b] = 0ull;
            }

            const float4* Wv = (const float4*)(W + og * 8);

#pragma unroll 4
            for (int k = 0; k < HH; k++) {
                double2 ha = *(const double2*)&hsT[k][rg * 8];
                double2 hb = *(const double2*)&hsT[k][rg * 8 + 4];
                u64 h0 = __double_as_longlong(ha.x);
                u64 h1 = __double_as_longlong(ha.y);
                u64 h2 = __double_as_longlong(hb.x);
                u64 h3 = __double_as_longlong(hb.y);
                float4 w0 = __ldg(Wv + k * 16);
                float4 w1 = __ldg(Wv + k * 16 + 1);
                u64 wb0 = pack2(w0.x), wb1 = pack2(w0.y), wb2 = pack2(w0.z), wb3 = pack2(w0.w);
                u64 wb4 = pack2(w1.x), wb5 = pack2(w1.y), wb6 = pack2(w1.z), wb7 = pack2(w1.w);

                fma2(acc2[0][0], h0, wb0); fma2(acc2[0][1], h0, wb1);
                fma2(acc2[0][2], h0, wb2); fma2(acc2[0][3], h0, wb3);
                fma2(acc2[0][4], h0, wb4); fma2(acc2[0][5], h0, wb5);
                fma2(acc2[0][6], h0, wb6); fma2(acc2[0][7], h0, wb7);

                fma2(acc2[1][0], h1, wb0); fma2(acc2[1][1], h1, wb1);
                fma2(acc2[1][2], h1, wb2); fma2(acc2[1][3], h1, wb3);
                fma2(acc2[1][4], h1, wb4); fma2(acc2[1][5], h1, wb5);
                fma2(acc2[1][6], h1, wb6); fma2(acc2[1][7], h1, wb7);

                fma2(acc2[2][0], h2, wb0); fma2(acc2[2][1], h2, wb1);
                fma2(acc2[2][2], h2, wb2); fma2(acc2[2][3], h2, wb3);
                fma2(acc2[2][4], h2, wb4); fma2(acc2[2][5], h2, wb5);
                fma2(acc2[2][6], h2, wb6); fma2(acc2[2][7], h2, wb7);

                fma2(acc2[3][0], h3, wb0); fma2(acc2[3][1], h3, wb1);
                fma2(acc2[3][2], h3, wb2); fma2(acc2[3][3], h3, wb3);
                fma2(acc2[3][4], h3, wb4); fma2(acc2[3][5], h3, wb5);
                fma2(acc2[3][6], h3, wb6); fma2(acc2[3][7], h3, wb7);
            }

#pragma unroll
            for (int ap = 0; ap < 4; ap++) {
                float2 u0 = unpack2(acc2[ap][0]);
                float2 u1 = unpack2(acc2[ap][1]);
                float2 u2 = unpack2(acc2[ap][2]);
                float2 u3 = unpack2(acc2[ap][3]);
                float2 u4 = unpack2(acc2[ap][4]);
                float2 u5 = unpack2(acc2[ap][5]);
                float2 u6 = unpack2(acc2[ap][6]);
                float2 u7 = unpack2(acc2[ap][7]);
                int dlo = sdst[rg * 8 + 2 * ap];
                int dhi = sdst[rg * 8 + 2 * ap + 1];
                if (dlo >= 0) {
                    float* dr = hout + dlo * HH + og * 8;
                    red_v4(dr,     u0.x, u1.x, u2.x, u3.x);
                    red_v4(dr + 4, u4.x, u5.x, u6.x, u7.x);
                }
                if (dhi >= 0) {
                    float* dr = hout + dhi * HH + og * 8;
                    red_v4(dr,     u0.y, u1.y, u2.y, u3.y);
                    red_v4(dr + 4, u4.y, u5.y, u6.y, u7.y);
                }
            }
        }

        if (iter < MPI - 1)
            grid_bar((unsigned)((iter + 1) * GRIDMP));
    }
}

// ======== fully fused Set2Set: 4 iterations + output MLP, 512 threads ======
// Chain-shortened: gate dot split across 2 threads/gate (96 MACs each),
// shift-free softmax (exp without max; shift-invariant, |e| << 80 so no
// overflow) fusing score+exp+sum into ONE pass with ONE reduction,
// pass-3 8-way split.
__global__ void k_s2s_all(const float* __restrict__ b_ih,
                          const float* __restrict__ b_hh,
                          const float* __restrict__ W_o1,
                          const float* __restrict__ b_o1,
                          const float* __restrict__ W_o2,
                          const float* __restrict__ b_o2,
                          float* __restrict__ out) {
    const float* h = g_hA;          // final node states after MPI=3 (A->B->C->A)
    int b = blockIdx.x;
    int tid = threadIdx.x;          // 512
    int lane = tid & 31;
    int wid = tid >> 5;             // 0..15

    __shared__ float hcache[SMAX * HH];   // 40KB
    __shared__ float sa[SA];
    __shared__ float qs[2 * HH];
    __shared__ float gates[4 * HH];       // half-0 partials then unused
    __shared__ float gpart[4 * HH];       // half-1 partials
    __shared__ float q[HH];
    __shared__ float hx_s[HH];
    __shared__ float cx_s[HH];
    __shared__ float red[16];
    __shared__ float r8[8][HH];

    int s = g_seg[b], t = g_seg[b + 1];
    int len = t - s;
    int nc = len < SMAX ? len : SMAX;

    {
        float4* d4 = (float4*)hcache;
        const float4* s4 = (const float4*)(h + s * HH);
        int tot = nc * (HH / 4);
        for (int i = tid; i < tot; i += 512) d4[i] = s4[i];
    }
    if (tid < 2 * HH) qs[tid] = 0.f;
    if (tid < HH) { hx_s[tid] = 0.f; cx_s[tid] = 0.f; }
    __syncthreads();

    for (int it = 0; it < S2S; it++) {
        // ---- gates: 2 threads per output, each half the k-range ----
        {
            int j = tid & 255;
            int half = tid >> 8;
            float ga, gb;
            if (half == 0) {
                ga = b_ih[j]; gb = 0.f;
#pragma unroll 16
                for (int k = 0; k < HH; k += 2) {
                    ga += qs[k]     * g_WihT[k * 256 + j];
                    gb += qs[k + 1] * g_WihT[(k + 1) * 256 + j];
                }
#pragma unroll 16
                for (int k = 0; k < HH / 2; k += 2) {
                    ga += hx_s[k]     * g_WhhT[k * 256 + j];
                    gb += hx_s[k + 1] * g_WhhT[(k + 1) * 256 + j];
                }
                gates[j] = ga + gb;
            } else {
                ga = b_hh[j]; gb = 0.f;
#pragma unroll 16
                for (int k = HH; k < 2 * HH; k += 2) {
                    ga += qs[k]     * g_WihT[k * 256 + j];
                    gb += qs[k + 1] * g_WihT[(k + 1) * 256 + j];
                }
#pragma unroll 16
                for (int k = HH / 2; k < HH; k += 2) {
                    ga += hx_s[k]     * g_WhhT[k * 256 + j];
                    gb += hx_s[k + 1] * g_WhhT[(k + 1) * 256 + j];
                }
                gpart[j] = ga + gb;
            }
        }
        __syncthreads();
        if (tid < HH) {
            float ig = gates[tid]          + gpart[tid];
            float fg = gates[HH + tid]     + gpart[HH + tid];
            float gg = gates[2 * HH + tid] + gpart[2 * HH + tid];
            float og = gates[3 * HH + tid] + gpart[3 * HH + tid];
            float si = 1.f / (1.f + expf(-ig));
            float sf = 1.f / (1.f + expf(-fg));
            float so = 1.f / (1.f + expf(-og));
            float c = sf * cx_s[tid] + si * tanhf(gg);
            cx_s[tid] = c;
            float hx = so * tanhf(c);
            hx_s[tid] = hx;
            q[tid] = hx;
        }
        __syncthreads();

        // ---- fused score+exp+sum (shift-free softmax, one reduction) ----
        float lsum = 0.f;
        const float4* q4 = (const float4*)q;
        for (int l = tid; l < len; l += 512) {
            const float4* hr = (l < nc) ? (const float4*)&hcache[l * HH]
                                        : (const float4*)(h + (s + l) * HH);
            float e = 0.f;
#pragma unroll
            for (int k = 0; k < HH / 4; k++) {
                float4 hv = hr[k];
                float4 qv = q4[k];
                e += hv.x * qv.x + hv.y * qv.y + hv.z * qv.z + hv.w * qv.w;
            }
            float a = expf(e);
            if (l < SA) sa[l] = a; else g_a[s + l] = a;
            lsum += a;
        }
        lsum = warp_sum(lsum);
        if (lane == 0) red[wid] = lsum;
        __syncthreads();
        if (tid < 16) {
            float v = red[tid];
#pragma unroll
            for (int o = 8; o > 0; o >>= 1)
                v += __shfl_xor_sync(0xffffu, v, o);
            if (tid == 0) red[0] = v;
        }
        __syncthreads();
        float denom = red[0];
        if (denom == 0.f) denom = 1.f;

        // ---- pass 3: r[o] = sum a*h / denom, 8-way n split ----
        {
            int part = tid >> 6;       // 0..7
            int o = tid & 63;
            float r0 = 0.f, r1 = 0.f;
            int l = part;
            for (; l + 8 < len; l += 16) {
                float av0 = (l < SA) ? sa[l] : g_a[s + l];
                float hv0 = (l < nc) ? hcache[l * HH + o] : h[(s + l) * HH + o];
                int l2 = l + 8;
                float av1 = (l2 < SA) ? sa[l2] : g_a[s + l2];
                float hv1 = (l2 < nc) ? hcache[l2 * HH + o] : h[(s + l2) * HH + o];
                r0 += av0 * hv0;
                r1 += av1 * hv1;
            }
            if (l < len) {
                float av = (l < SA) ? sa[l] : g_a[s + l];
                float hv = (l < nc) ? hcache[l * HH + o] : h[(s + l) * HH + o];
                r0 += av * hv;
            }
            r8[part][o] = r0 + r1;
        }
        __syncthreads();
        if (tid < HH) {
            float r = (r8[0][tid] + r8[1][tid] + r8[2][tid] + r8[3][tid] +
                       r8[4][tid] + r8[5][tid] + r8[6][tid] + r8[7][tid]) / denom;
            qs[tid]      = q[tid];
            qs[HH + tid] = r;
        }
        __syncthreads();
    }

    // ---- output MLP (warp-shuffle final reduction) ----
    float contrib = 0.f;
    if (tid < HH) {
        float v = b_o1[tid];
#pragma unroll 8
        for (int k = 0; k < 2 * HH; k++) v += qs[k] * W_o1[k * HH + tid];
        v = fmaxf(v, 0.f);
        contrib = v * W_o2[tid];
    }
    if (wid < 2) {
        contrib = warp_sum(contrib);
        if (lane == 0) red[wid] = contrib;
    }
    __syncthreads();
    if (tid == 0) out[b] = red[0] + red[1] + b_o2[0];
}

// ---------------------------------------------------------------------------
extern "C" void kernel_launch(void* const* d_in, const int* in_sizes, int n_in,
                              void* d_out, int out_size) {
    const float* node_feat = (const float*)d_in[0];
    const int*   node_type = (const int*)d_in[1];
    const int*   edge_index= (const int*)d_in[2];
    const int*   etype     = (const int*)d_in[3];
    const int*   batch     = (const int*)d_in[4];
    const float* W_emb     = (const float*)d_in[5];
    const float* b_emb     = (const float*)d_in[6];
    const float* W_e1      = (const float*)d_in[7];
    const float* b_e1      = (const float*)d_in[8];
    const float* W_e2      = (const float*)d_in[9];
    const float* b_e2      = (const float*)d_in[10];
    const float* roots     = (const float*)d_in[11];
    const float* conv_bias = (const float*)d_in[12];
    const float* W_ih      = (const float*)d_in[13];
    const float* W_hh      = (const float*)d_in[14];
    const float* b_ih      = (const float*)d_in[15];
    const float* b_hh      = (const float*)d_in[16];
    const float* W_o1      = (const float*)d_in[17];
    const float* b_o1      = (const float*)d_in[18];
    const float* W_o2      = (const float*)d_in[19];
    const float* b_o2      = (const float*)d_in[20];
    float* out = (float*)d_out;

    const int* src = edge_index;
    const int* dst = edge_index + EE;

    k_setup<<<(EE + 255) / 256, 256>>>(batch, etype);
    k_front<<<SCB + 66 + NN / 4, 256>>>(etype, src, dst,
                                        W_e1, b_e1, W_e2, b_e2,
                                        node_feat, node_type, W_emb, b_emb,
                                        W_ih, W_hh);

    // persistent MP: all 3 iterations, device-wide barriers between them
    k_mp_all<<<GRIDMP, 128>>>(roots, conv_bias);

    k_s2s_all<<<BB, 512>>>(b_ih, b_hh, W_o1, b_o1, W_o2, b_o2, out);
}